// round 16
// baseline (speedup 1.0000x reference)
#include <cuda_runtime.h>
#include <math.h>
#include <cstdint>

#define Hh 160
#define Ww 160
#define HWp 25600
#define Cc 64
#define OUTC 64
#define Bb 4

// scratch: precomputed sample coords + mask, [B][9][H*W]
__device__ float g_py[Bb * 9 * HWp];
__device__ float g_px[Bb * 9 * HWp];
__device__ float g_m [Bb * 9 * HWp];
// transposed input: [b][pix][c] (c contiguous)
__device__ float g_xT[(size_t)Bb * HWp * Cc];
// transposed dcn weights: [k][c][o]
__device__ float g_dwT[9 * Cc * OUTC];

__device__ __forceinline__ unsigned long long pk2(float lo, float hi) {
    unsigned long long r;
    asm("mov.b64 %0,{%1,%2};" : "=l"(r) : "f"(lo), "f"(hi));
    return r;
}
__device__ __forceinline__ void upk2(unsigned long long v, float& lo, float& hi) {
    asm("mov.b64 {%0,%1},%2;" : "=f"(lo), "=f"(hi) : "l"(v));
}
__device__ __forceinline__ void fma2(unsigned long long& d, unsigned long long a, unsigned long long b) {
    asm("fma.rn.f32x2 %0,%1,%2,%0;" : "+l"(d) : "l"(a), "l"(b));
}

__device__ __forceinline__ uint32_t smem_to_u32(const void* p) {
    uint32_t a;
    asm("{ .reg .u64 t; cvta.to.shared.u64 t, %1; cvt.u32.u64 %0, t; }" : "=r"(a) : "l"(p));
    return a;
}
#define MBARRIER_INIT(mb, c) \
    asm volatile("mbarrier.init.shared.b64 [%0], %1;" :: "r"((uint32_t)(mb)), "r"((uint32_t)(c)) : "memory")
#define MBARRIER_ARRIVE(mb) \
    asm volatile("mbarrier.arrive.shared.b64 _, [%0];" :: "r"((uint32_t)(mb)) : "memory")
#define MBARRIER_WAIT_PARITY(mb, par) do {                                              \
    uint32_t _m = (uint32_t)(mb); uint32_t _p = (uint32_t)(par); uint32_t _d;           \
    asm volatile("{\n\t.reg .pred p;\n\t"                                               \
        "mbarrier.try_wait.parity.acquire.cta.shared::cta.b64 p, [%1], %2;\n\t"         \
        "selp.b32 %0, 1, 0, p;\n\t}" : "=r"(_d) : "r"(_m), "r"(_p) : "memory");         \
    if (!_d) {                                                                          \
        asm volatile("{\n\t.reg .pred P1;\n\t"                                          \
            "WL_%=:\n\t"                                                                \
            "mbarrier.try_wait.parity.acquire.cta.shared::cta.b64 P1, [%0], %1, 0x989680;\n\t" \
            "@P1 bra.uni WD_%=;\n\t"                                                    \
            "bra.uni WL_%=;\n\t"                                                        \
            "WD_%=:\n\t}" :: "r"(_m), "r"(_p) : "memory");                              \
    }                                                                                   \
} while (0)

// ============================================================================
// Prep A: transpose x[b][c][p] -> g_xT[b][p][c]
// ============================================================================
__global__ void __launch_bounds__(256) xpose_kernel(const float* __restrict__ x)
{
    __shared__ float t[32][33];
    const int b  = blockIdx.z;
    const int c0 = blockIdx.y * 32;
    const int p0 = blockIdx.x * 32;
    const int tx = threadIdx.x, ty = threadIdx.y;

    const float* xb = x + ((size_t)b * Cc + c0) * HWp + p0;
#pragma unroll
    for (int i = 0; i < 4; i++)
        t[ty + i * 8][tx] = xb[(size_t)(ty + i * 8) * HWp + tx];
    __syncthreads();
    float* o = g_xT + ((size_t)b * HWp + p0) * Cc + c0;
#pragma unroll
    for (int i = 0; i < 4; i++)
        o[(size_t)(ty + i * 8) * Cc + tx] = t[tx][ty + i * 8];
}

// ============================================================================
// Prep B: transpose dcn_w[o][c][k] -> g_dwT[k][c][o]
// ============================================================================
__global__ void __launch_bounds__(256) wpose_kernel(const float* __restrict__ dw)
{
    int idx = blockIdx.x * 256 + threadIdx.x;   // 144*256 = 36864 exactly
    int k = idx >> 12;
    int c = (idx >> 6) & 63;
    int o = idx & 63;
    g_dwT[idx] = dw[(o * 64 + c) * 9 + k];
}

// ============================================================================
// Kernel 1: offset(18ch)+mask(9ch) 3x3 conv. 128 threads, 2 pixels/thread,
// grid 400. (REVERTED to the proven round-13/14 version.)
// ============================================================================
__global__ void __launch_bounds__(128) omconv_kernel(
    const float* __restrict__ x,
    const float* __restrict__ ow, const float* __restrict__ ob,
    const float* __restrict__ mw, const float* __restrict__ mb)
{
    extern __shared__ float Wsh[];  // [64][9][28]
    const int tid = threadIdx.x;

    for (int idx = tid; idx < 64 * 9 * 28; idx += 128) {
        int o = idx % 28;
        int ck = idx / 28;
        int t = ck % 9;
        int c = ck / 9;
        float w;
        if (o < 18)      w = ow[(o * 64 + c) * 9 + t];
        else if (o < 27) w = mw[((o - 18) * 64 + c) * 9 + t];
        else             w = 0.f;
        Wsh[idx] = w;
    }
    __syncthreads();

    const int base = blockIdx.x * 256;
    const int b = base / HWp;
    const int pbb = base - b * HWp;

    int pl[2];  pl[0] = pbb + tid;  pl[1] = pbb + tid + 128;
    int ii[2], jj[2];
    int  ioff[2][9];
    bool vld[2][9];
#pragma unroll
    for (int q = 0; q < 2; q++) {
        ii[q] = pl[q] / Ww;
        jj[q] = pl[q] - ii[q] * Ww;
#pragma unroll
        for (int t = 0; t < 9; t++) {
            int yy = ii[q] + t / 3 - 1;
            int xx = jj[q] + t % 3 - 1;
            vld[q][t] = (yy >= 0) && (yy < Hh) && (xx >= 0) && (xx < Ww);
            int yc = min(max(yy, 0), Hh - 1);
            int xc = min(max(xx, 0), Ww - 1);
            ioff[q][t] = yc * Ww + xc;
        }
    }

    unsigned long long acc[2][14];
#pragma unroll
    for (int u = 0; u < 14; u++) {
        int o0 = 2 * u, o1 = 2 * u + 1;
        float blo = (o0 < 18) ? ob[o0] : mb[o0 - 18];
        float bhi = (o1 < 18) ? ob[o1] : ((o1 < 27) ? mb[o1 - 18] : 0.f);
        unsigned long long bb = pk2(blo, bhi);
        acc[0][u] = bb;  acc[1][u] = bb;
    }

    const float* xb = x + (size_t)b * Cc * HWp;

    for (int c = 0; c < 64; c++) {
        const float* xc = xb + c * HWp;
        float v[2][9];
#pragma unroll
        for (int q = 0; q < 2; q++)
#pragma unroll
            for (int t = 0; t < 9; t++)
                v[q][t] = vld[q][t] ? __ldg(xc + ioff[q][t]) : 0.f;
#pragma unroll
        for (int t = 0; t < 9; t++) {
            unsigned long long v0 = pk2(v[0][t], v[0][t]);
            unsigned long long v1 = pk2(v[1][t], v[1][t]);
            const ulonglong2* wr = (const ulonglong2*)(Wsh + (c * 9 + t) * 28);
#pragma unroll
            for (int u = 0; u < 7; u++) {
                ulonglong2 w2 = wr[u];
                fma2(acc[0][2 * u],     w2.x, v0);
                fma2(acc[0][2 * u + 1], w2.y, v0);
                fma2(acc[1][2 * u],     w2.x, v1);
                fma2(acc[1][2 * u + 1], w2.y, v1);
            }
        }
    }

#pragma unroll
    for (int q = 0; q < 2; q++) {
        float accf[28];
#pragma unroll
        for (int u = 0; u < 14; u++) upk2(acc[q][u], accf[2 * u], accf[2 * u + 1]);
#pragma unroll
        for (int k = 0; k < 9; k++) {
            float m = 1.f / (1.f + expf(-accf[18 + k]));
            float py = accf[2 * k]     + (float)(ii[q] - 1 + k / 3);
            float px = accf[2 * k + 1] + (float)(jj[q] - 1 + k % 3);
            int o = (b * 9 + k) * HWp + pl[q];
            g_py[o] = py;
            g_px[o] = px;
            g_m[o]  = m;
        }
    }
}

// ============================================================================
// Kernel 2: warp-specialized DCN GEMM, 256 threads, TILE=128, 2 blocks/SM.
// CHANGES vs round-13: A-operand (weights) read directly from g_dwT via
// broadcast LDG (L1-resident, 147KB) -> no W staging, S-only stages ->
// 3-deep pipeline to absorb per-tap producer jitter.
// ============================================================================
static constexpr int TILE     = 128;
static constexpr int NSTG     = 3;
// mbarriers: full[s] at s*16, empty[s] at s*16+8  (s = 0..2)
static constexpr int SCR0     = 128;                      // 3 x 4KB scratch
static constexpr int BUF0     = SCR0 + NSTG * 4096;       // 12416
static constexpr int BUFSZ    = 64 * TILE * 4;            // S: 32768 B
static constexpr int SMEM_WS  = BUF0 + NSTG * BUFSZ;      // 110720 B/block

__global__ void __launch_bounds__(256, 2) dcn_ws_kernel(
    float* __restrict__ out)
{
    extern __shared__ char smc[];
    const uint32_t sb = smem_to_u32(smc);
    const int tid = threadIdx.x;

    const int b = blockIdx.x / 200;               // 200 tiles of 128 pix per image
    const int pbase = (blockIdx.x % 200) * TILE;

    if (tid == 0) {
#pragma unroll
        for (int s = 0; s < NSTG; s++) {
            MBARRIER_INIT(sb + s * 16,     128);  // full
            MBARRIER_INIT(sb + s * 16 + 8, 128);  // empty
        }
    }
    __syncthreads();

    if (tid >= 128) {
        // ---------------- PRODUCER (4 warps) ----------------
        const int stid = tid - 128;               // 0..127
        const int wp   = stid >> 5;               // producer warp 0..3
        const int half = (stid >> 4) & 1;         // pixel-pair within quad
        const int c4   = stid & 15;               // 4-channel group
        const float* xTb = g_xT + (size_t)b * HWp * Cc;

        for (int k = 0; k < 9; k++) {
            const int s = k % NSTG;
            if (k >= NSTG)
                MBARRIER_WAIT_PARITY(sb + s * 16 + 8, ((k / NSTG) - 1) & 1);

            float* Sbuf = (float*)(smc + BUF0 + s * BUFSZ);
            float4* wbuf = (float4*)(smc + SCR0 + s * 4096);
            int4*   ibuf = (int4*)(smc + SCR0 + s * 4096 + 2048);

            // phase A: geometry for pixel stid
            {
                int gi = (b * 9 + k) * HWp + pbase + stid;
                float py = g_py[gi], px = g_px[gi], m = g_m[gi];
                float y0f = floorf(py), x0f = floorf(px);
                int y0 = (int)y0f, x0 = (int)x0f;
                float wy1 = py - y0f, wx1 = px - x0f;
                float wy0 = 1.f - wy1, wx0 = 1.f - wx1;
                bool yv0 = (y0 >= 0) && (y0 < Hh);
                bool yv1 = (y0 + 1 >= 0) && (y0 + 1 < Hh);
                bool xv0 = (x0 >= 0) && (x0 < Ww);
                bool xv1 = (x0 + 1 >= 0) && (x0 + 1 < Ww);
                float w00 = (yv0 && xv0) ? wy0 * wx0 * m : 0.f;
                float w01 = (yv0 && xv1) ? wy0 * wx1 * m : 0.f;
                float w10 = (yv1 && xv0) ? wy1 * wx0 * m : 0.f;
                float w11 = (yv1 && xv1) ? wy1 * wx1 * m : 0.f;
                int y0c = min(max(y0, 0), Hh - 1);
                int y1c = min(max(y0 + 1, 0), Hh - 1);
                int x0c = min(max(x0, 0), Ww - 1);
                int x1c = min(max(x0 + 1, 0), Ww - 1);
                wbuf[stid] = make_float4(w00, w01, w10, w11);
                ibuf[stid] = make_int4(y0c * Ww + x0c, y0c * Ww + x1c,
                                       y1c * Ww + x0c, y1c * Ww + x1c);
            }
            asm volatile("bar.sync 1, 128;" ::: "memory");

            // phase B: each thread = pixel pair (p, p+1), 4 channels
#pragma unroll 4
            for (int it = 0; it < 8; it++) {
                int p = wp * 32 + it * 4 + half * 2;   // even
                float4 wa = wbuf[p],     wb = wbuf[p + 1];
                int4   ia = ibuf[p],     ib = ibuf[p + 1];
                const float4* a00 = (const float4*)(xTb + (size_t)ia.x * Cc) + c4;
                const float4* a01 = (const float4*)(xTb + (size_t)ia.y * Cc) + c4;
                const float4* a10 = (const float4*)(xTb + (size_t)ia.z * Cc) + c4;
                const float4* a11 = (const float4*)(xTb + (size_t)ia.w * Cc) + c4;
                const float4* b00 = (const float4*)(xTb + (size_t)ib.x * Cc) + c4;
                const float4* b01 = (const float4*)(xTb + (size_t)ib.y * Cc) + c4;
                const float4* b10 = (const float4*)(xTb + (size_t)ib.z * Cc) + c4;
                const float4* b11 = (const float4*)(xTb + (size_t)ib.w * Cc) + c4;
                float4 va0 = __ldg(a00), va1 = __ldg(a01), va2 = __ldg(a10), va3 = __ldg(a11);
                float4 vb0 = __ldg(b00), vb1 = __ldg(b01), vb2 = __ldg(b10), vb3 = __ldg(b11);
                float sa[4], sbv[4];
                sa[0] = wa.x * va0.x + wa.y * va1.x + wa.z * va2.x + wa.w * va3.x;
                sa[1] = wa.x * va0.y + wa.y * va1.y + wa.z * va2.y + wa.w * va3.y;
                sa[2] = wa.x * va0.z + wa.y * va1.z + wa.z * va2.z + wa.w * va3.z;
                sa[3] = wa.x * va0.w + wa.y * va1.w + wa.z * va2.w + wa.w * va3.w;
                sbv[0] = wb.x * vb0.x + wb.y * vb1.x + wb.z * vb2.x + wb.w * vb3.x;
                sbv[1] = wb.x * vb0.y + wb.y * vb1.y + wb.z * vb2.y + wb.w * vb3.y;
                sbv[2] = wb.x * vb0.z + wb.y * vb1.z + wb.z * vb2.z + wb.w * vb3.z;
                sbv[3] = wb.x * vb0.w + wb.y * vb1.w + wb.z * vb2.w + wb.w * vb3.w;
                // swizzled STS.64: quad q = p>>2, q' = q ^ c4
                int q  = p >> 2;
                int qs = q ^ c4;
                float2* Sr = (float2*)(Sbuf + (c4 * 4) * TILE + qs * 4 + half * 2);
#pragma unroll
                for (int u = 0; u < 4; u++)
                    Sr[u * (TILE / 2)] = make_float2(sa[u], sbv[u]);
            }

            MBARRIER_ARRIVE(sb + s * 16);   // full[s]
        }
    } else {
        // ---------------- CONSUMER (4 warps) ----------------
        const int tx = tid & 31;                  // pixel quad (4 pix each)
        const int ty = tid >> 5;                  // o group (16 o each)

        unsigned long long acc[16][2];
#pragma unroll
        for (int oi = 0; oi < 16; oi++) { acc[oi][0] = 0ull; acc[oi][1] = 0ull; }

        for (int k = 0; k < 9; k++) {
            const int s = k % NSTG;
            MBARRIER_WAIT_PARITY(sb + s * 16, (k / NSTG) & 1);

            const ulonglong2* Sq = (const ulonglong2*)(smc + BUF0 + s * BUFSZ);
            const float4* Wk = (const float4*)(g_dwT + k * 4096);  // [c][o] row 64

#pragma unroll 8
            for (int cc = 0; cc < 64; cc++) {
                int sw = cc >> 2;
                ulonglong2 B = Sq[cc * 32 + (tx ^ sw)];   // 4 pixels, conflict-free
                unsigned long long b0 = B.x, b1 = B.y;
#pragma unroll
                for (int g = 0; g < 4; g++) {
                    float4 av = __ldg(Wk + cc * 16 + ty * 4 + g);  // broadcast LDG, L1-hot
                    unsigned long long a0 = pk2(av.x, av.x);
                    unsigned long long a1 = pk2(av.y, av.y);
                    unsigned long long a2 = pk2(av.z, av.z);
                    unsigned long long a3 = pk2(av.w, av.w);
                    fma2(acc[g * 4 + 0][0], a0, b0); fma2(acc[g * 4 + 0][1], a0, b1);
                    fma2(acc[g * 4 + 1][0], a1, b0); fma2(acc[g * 4 + 1][1], a1, b1);
                    fma2(acc[g * 4 + 2][0], a2, b0); fma2(acc[g * 4 + 2][1], a2, b1);
                    fma2(acc[g * 4 + 3][0], a3, b0); fma2(acc[g * 4 + 3][1], a3, b1);
                }
            }

            MBARRIER_ARRIVE(sb + s * 16 + 8);   // empty[s]
        }

        // epilogue: 16 o rows x one float4 of pixels
        const int p0 = pbase + tx * 4;
        float* obp = out + (size_t)(b * 64 + ty * 16) * HWp + p0;
#pragma unroll
        for (int oi = 0; oi < 16; oi++) {
            float4 v;
            upk2(acc[oi][0], v.x, v.y);
            upk2(acc[oi][1], v.z, v.w);
            *(float4*)(obp + (size_t)oi * HWp) = v;
        }
    }
}

extern "C" void kernel_launch(void* const* d_in, const int* in_sizes, int n_in,
                              void* d_out, int out_size)
{
    const float* x        = (const float*)d_in[0];
    const float* offset_w = (const float*)d_in[1];
    const float* offset_b = (const float*)d_in[2];
    const float* mask_w   = (const float*)d_in[3];
    const float* mask_b   = (const float*)d_in[4];
    const float* dcn_w    = (const float*)d_in[5];
    float* out = (float*)d_out;

    const int smem1 = 64 * 9 * 28 * 4;      // 64512 B
    cudaFuncSetAttribute(omconv_kernel, cudaFuncAttributeMaxDynamicSharedMemorySize, smem1);
    cudaFuncSetAttribute(dcn_ws_kernel, cudaFuncAttributeMaxDynamicSharedMemorySize, SMEM_WS);

    xpose_kernel<<<dim3(800, 2, 4), dim3(32, 8)>>>(x);
    wpose_kernel<<<144, 256>>>(dcn_w);
    omconv_kernel<<<400, 128, smem1>>>(x, offset_w, offset_b, mask_w, mask_b);
    dcn_ws_kernel<<<800, 256, SMEM_WS>>>(out);
}

// round 17
// speedup vs baseline: 1.2441x; 1.2441x over previous
#include <cuda_runtime.h>
#include <math.h>
#include <cstdint>

#define Hh 160
#define Ww 160
#define HWp 25600
#define Cc 64
#define OUTC 64
#define Bb 4

// scratch: precomputed sample coords + mask, [B][9][H*W]
__device__ float g_py[Bb * 9 * HWp];
__device__ float g_px[Bb * 9 * HWp];
__device__ float g_m [Bb * 9 * HWp];
// transposed input: [b][pix][c] (c contiguous)
__device__ float g_xT[(size_t)Bb * HWp * Cc];
// transposed dcn weights: [k][c][o]
__device__ float g_dwT[9 * Cc * OUTC];

__device__ __forceinline__ unsigned long long pk2(float lo, float hi) {
    unsigned long long r;
    asm("mov.b64 %0,{%1,%2};" : "=l"(r) : "f"(lo), "f"(hi));
    return r;
}
__device__ __forceinline__ void upk2(unsigned long long v, float& lo, float& hi) {
    asm("mov.b64 {%0,%1},%2;" : "=f"(lo), "=f"(hi) : "l"(v));
}
__device__ __forceinline__ void fma2(unsigned long long& d, unsigned long long a, unsigned long long b) {
    asm("fma.rn.f32x2 %0,%1,%2,%0;" : "+l"(d) : "l"(a), "l"(b));
}

__device__ __forceinline__ uint32_t smem_to_u32(const void* p) {
    uint32_t a;
    asm("{ .reg .u64 t; cvta.to.shared.u64 t, %1; cvt.u32.u64 %0, t; }" : "=r"(a) : "l"(p));
    return a;
}
#define MBARRIER_INIT(mb, c) \
    asm volatile("mbarrier.init.shared.b64 [%0], %1;" :: "r"((uint32_t)(mb)), "r"((uint32_t)(c)) : "memory")
#define MBARRIER_ARRIVE(mb) \
    asm volatile("mbarrier.arrive.shared.b64 _, [%0];" :: "r"((uint32_t)(mb)) : "memory")
#define MBARRIER_WAIT_PARITY(mb, par) do {                                              \
    uint32_t _m = (uint32_t)(mb); uint32_t _p = (uint32_t)(par); uint32_t _d;           \
    asm volatile("{\n\t.reg .pred p;\n\t"                                               \
        "mbarrier.try_wait.parity.acquire.cta.shared::cta.b64 p, [%1], %2;\n\t"         \
        "selp.b32 %0, 1, 0, p;\n\t}" : "=r"(_d) : "r"(_m), "r"(_p) : "memory");         \
    if (!_d) {                                                                          \
        asm volatile("{\n\t.reg .pred P1;\n\t"                                          \
            "WL_%=:\n\t"                                                                \
            "mbarrier.try_wait.parity.acquire.cta.shared::cta.b64 P1, [%0], %1, 0x989680;\n\t" \
            "@P1 bra.uni WD_%=;\n\t"                                                    \
            "bra.uni WL_%=;\n\t"                                                        \
            "WD_%=:\n\t}" :: "r"(_m), "r"(_p) : "memory");                              \
    }                                                                                   \
} while (0)

// ============================================================================
// Prep A: transpose x[b][c][p] -> g_xT[b][p][c]
// ============================================================================
__global__ void __launch_bounds__(256) xpose_kernel(const float* __restrict__ x)
{
    __shared__ float t[32][33];
    const int b  = blockIdx.z;
    const int c0 = blockIdx.y * 32;
    const int p0 = blockIdx.x * 32;
    const int tx = threadIdx.x, ty = threadIdx.y;

    const float* xb = x + ((size_t)b * Cc + c0) * HWp + p0;
#pragma unroll
    for (int i = 0; i < 4; i++)
        t[ty + i * 8][tx] = xb[(size_t)(ty + i * 8) * HWp + tx];
    __syncthreads();
    float* o = g_xT + ((size_t)b * HWp + p0) * Cc + c0;
#pragma unroll
    for (int i = 0; i < 4; i++)
        o[(size_t)(ty + i * 8) * Cc + tx] = t[tx][ty + i * 8];
}

// ============================================================================
// Prep B: transpose dcn_w[o][c][k] -> g_dwT[k][c][o]
// ============================================================================
__global__ void __launch_bounds__(256) wpose_kernel(const float* __restrict__ dw)
{
    int idx = blockIdx.x * 256 + threadIdx.x;   // 144*256 = 36864 exactly
    int k = idx >> 12;
    int c = (idx >> 6) & 63;
    int o = idx & 63;
    g_dwT[idx] = dw[(o * 64 + c) * 9 + k];
}

// ============================================================================
// Kernel 1: offset(18ch)+mask(9ch) 3x3 conv. 128 threads, 2 pixels/thread,
// grid 400. Round-13/14 structure; ONLY change: c-loop unroll 2 to double
// the in-flight LDG window (latency-bound at ~2.7 warps/SMSP).
// ============================================================================
__global__ void __launch_bounds__(128) omconv_kernel(
    const float* __restrict__ x,
    const float* __restrict__ ow, const float* __restrict__ ob,
    const float* __restrict__ mw, const float* __restrict__ mb)
{
    extern __shared__ float Wsh[];  // [64][9][28]
    const int tid = threadIdx.x;

    for (int idx = tid; idx < 64 * 9 * 28; idx += 128) {
        int o = idx % 28;
        int ck = idx / 28;
        int t = ck % 9;
        int c = ck / 9;
        float w;
        if (o < 18)      w = ow[(o * 64 + c) * 9 + t];
        else if (o < 27) w = mw[((o - 18) * 64 + c) * 9 + t];
        else             w = 0.f;
        Wsh[idx] = w;
    }
    __syncthreads();

    const int base = blockIdx.x * 256;
    const int b = base / HWp;
    const int pbb = base - b * HWp;

    int pl[2];  pl[0] = pbb + tid;  pl[1] = pbb + tid + 128;
    int ii[2], jj[2];
    int  ioff[2][9];
    bool vld[2][9];
#pragma unroll
    for (int q = 0; q < 2; q++) {
        ii[q] = pl[q] / Ww;
        jj[q] = pl[q] - ii[q] * Ww;
#pragma unroll
        for (int t = 0; t < 9; t++) {
            int yy = ii[q] + t / 3 - 1;
            int xx = jj[q] + t % 3 - 1;
            vld[q][t] = (yy >= 0) && (yy < Hh) && (xx >= 0) && (xx < Ww);
            int yc = min(max(yy, 0), Hh - 1);
            int xc = min(max(xx, 0), Ww - 1);
            ioff[q][t] = yc * Ww + xc;
        }
    }

    unsigned long long acc[2][14];
#pragma unroll
    for (int u = 0; u < 14; u++) {
        int o0 = 2 * u, o1 = 2 * u + 1;
        float blo = (o0 < 18) ? ob[o0] : mb[o0 - 18];
        float bhi = (o1 < 18) ? ob[o1] : ((o1 < 27) ? mb[o1 - 18] : 0.f);
        unsigned long long bb = pk2(blo, bhi);
        acc[0][u] = bb;  acc[1][u] = bb;
    }

    const float* xb = x + (size_t)b * Cc * HWp;

#pragma unroll 2
    for (int c = 0; c < 64; c++) {
        const float* xc = xb + c * HWp;
        float v[2][9];
#pragma unroll
        for (int q = 0; q < 2; q++)
#pragma unroll
            for (int t = 0; t < 9; t++)
                v[q][t] = vld[q][t] ? __ldg(xc + ioff[q][t]) : 0.f;
#pragma unroll
        for (int t = 0; t < 9; t++) {
            unsigned long long v0 = pk2(v[0][t], v[0][t]);
            unsigned long long v1 = pk2(v[1][t], v[1][t]);
            const ulonglong2* wr = (const ulonglong2*)(Wsh + (c * 9 + t) * 28);
#pragma unroll
            for (int u = 0; u < 7; u++) {
                ulonglong2 w2 = wr[u];
                fma2(acc[0][2 * u],     w2.x, v0);
                fma2(acc[0][2 * u + 1], w2.y, v0);
                fma2(acc[1][2 * u],     w2.x, v1);
                fma2(acc[1][2 * u + 1], w2.y, v1);
            }
        }
    }

#pragma unroll
    for (int q = 0; q < 2; q++) {
        float accf[28];
#pragma unroll
        for (int u = 0; u < 14; u++) upk2(acc[q][u], accf[2 * u], accf[2 * u + 1]);
#pragma unroll
        for (int k = 0; k < 9; k++) {
            float m = 1.f / (1.f + expf(-accf[18 + k]));
            float py = accf[2 * k]     + (float)(ii[q] - 1 + k / 3);
            float px = accf[2 * k + 1] + (float)(jj[q] - 1 + k % 3);
            int o = (b * 9 + k) * HWp + pl[q];
            g_py[o] = py;
            g_px[o] = px;
            g_m[o]  = m;
        }
    }
}

// ============================================================================
// Kernel 2: warp-specialized DCN GEMM, 256 threads, TILE=128, 2 blocks/SM.
// EXACT round-13/14 version (proven 185.7us): Ws staged in smem per tap,
// 2-stage double buffer, 16B-granule swizzle, consumer 16o x 4pix.
// ============================================================================
static constexpr int TILE     = 128;
static constexpr int MB_FULL0 = 0;    // +s*8
static constexpr int MB_EMPT0 = 16;   // +s*8
static constexpr int SCR0     = 128;                      // 2 x 4KB scratch
static constexpr int BUF0     = SCR0 + 8192;              // 8320
static constexpr int BUFSZ    = 16384 + 32768;            // Ws 16KB + S 32KB
static constexpr int SMEM_WS  = BUF0 + 2 * BUFSZ;         // 106624 B/block

__global__ void __launch_bounds__(256, 2) dcn_ws_kernel(
    float* __restrict__ out)
{
    extern __shared__ char smc[];
    const uint32_t sb = smem_to_u32(smc);
    const int tid = threadIdx.x;

    const int b = blockIdx.x / 200;               // 200 tiles of 128 pix per image
    const int pbase = (blockIdx.x % 200) * TILE;

    if (tid == 0) {
        MBARRIER_INIT(sb + MB_FULL0,     128);
        MBARRIER_INIT(sb + MB_FULL0 + 8, 128);
        MBARRIER_INIT(sb + MB_EMPT0,     128);
        MBARRIER_INIT(sb + MB_EMPT0 + 8, 128);
    }
    __syncthreads();

    if (tid >= 128) {
        // ---------------- PRODUCER (4 warps) ----------------
        const int stid = tid - 128;               // 0..127
        const int wp   = stid >> 5;               // producer warp 0..3
        const int half = (stid >> 4) & 1;         // pixel-pair within quad
        const int c4   = stid & 15;               // 4-channel group
        const float* xTb = g_xT + (size_t)b * HWp * Cc;

        for (int k = 0; k < 9; k++) {
            const int s = k & 1;
            const int n = k >> 1;
            if (k >= 2) MBARRIER_WAIT_PARITY(sb + MB_EMPT0 + s * 8, (n - 1) & 1);

            float4* Ws4  = (float4*)(smc + BUF0 + s * BUFSZ);
            float*  Sbuf = (float*)(smc + BUF0 + s * BUFSZ + 16384);
            float4* wbuf = (float4*)(smc + SCR0 + s * 4096);
            int4*   ibuf = (int4*)(smc + SCR0 + s * 4096 + 2048);

            // stage Wk (contiguous from g_dwT[k]) : 8 float4 per thread
            {
                const float4* src = (const float4*)(g_dwT + k * 4096);
#pragma unroll
                for (int r = 0; r < 8; r++)
                    Ws4[stid + r * 128] = __ldg(src + stid + r * 128);
            }

            // phase A: geometry for pixel stid
            {
                int gi = (b * 9 + k) * HWp + pbase + stid;
                float py = g_py[gi], px = g_px[gi], m = g_m[gi];
                float y0f = floorf(py), x0f = floorf(px);
                int y0 = (int)y0f, x0 = (int)x0f;
                float wy1 = py - y0f, wx1 = px - x0f;
                float wy0 = 1.f - wy1, wx0 = 1.f - wx1;
                bool yv0 = (y0 >= 0) && (y0 < Hh);
                bool yv1 = (y0 + 1 >= 0) && (y0 + 1 < Hh);
                bool xv0 = (x0 >= 0) && (x0 < Ww);
                bool xv1 = (x0 + 1 >= 0) && (x0 + 1 < Ww);
                float w00 = (yv0 && xv0) ? wy0 * wx0 * m : 0.f;
                float w01 = (yv0 && xv1) ? wy0 * wx1 * m : 0.f;
                float w10 = (yv1 && xv0) ? wy1 * wx0 * m : 0.f;
                float w11 = (yv1 && xv1) ? wy1 * wx1 * m : 0.f;
                int y0c = min(max(y0, 0), Hh - 1);
                int y1c = min(max(y0 + 1, 0), Hh - 1);
                int x0c = min(max(x0, 0), Ww - 1);
                int x1c = min(max(x0 + 1, 0), Ww - 1);
                wbuf[stid] = make_float4(w00, w01, w10, w11);
                ibuf[stid] = make_int4(y0c * Ww + x0c, y0c * Ww + x1c,
                                       y1c * Ww + x0c, y1c * Ww + x1c);
            }
            asm volatile("bar.sync 1, 128;" ::: "memory");

            // phase B: each thread = pixel pair (p, p+1), 4 channels
#pragma unroll 4
            for (int it = 0; it < 8; it++) {
                int p = wp * 32 + it * 4 + half * 2;   // even
                float4 wa = wbuf[p],     wb = wbuf[p + 1];
                int4   ia = ibuf[p],     ib = ibuf[p + 1];
                const float4* a00 = (const float4*)(xTb + (size_t)ia.x * Cc) + c4;
                const float4* a01 = (const float4*)(xTb + (size_t)ia.y * Cc) + c4;
                const float4* a10 = (const float4*)(xTb + (size_t)ia.z * Cc) + c4;
                const float4* a11 = (const float4*)(xTb + (size_t)ia.w * Cc) + c4;
                const float4* b00 = (const float4*)(xTb + (size_t)ib.x * Cc) + c4;
                const float4* b01 = (const float4*)(xTb + (size_t)ib.y * Cc) + c4;
                const float4* b10 = (const float4*)(xTb + (size_t)ib.z * Cc) + c4;
                const float4* b11 = (const float4*)(xTb + (size_t)ib.w * Cc) + c4;
                float4 va0 = __ldg(a00), va1 = __ldg(a01), va2 = __ldg(a10), va3 = __ldg(a11);
                float4 vb0 = __ldg(b00), vb1 = __ldg(b01), vb2 = __ldg(b10), vb3 = __ldg(b11);
                float sa[4], sbv[4];
                sa[0] = wa.x * va0.x + wa.y * va1.x + wa.z * va2.x + wa.w * va3.x;
                sa[1] = wa.x * va0.y + wa.y * va1.y + wa.z * va2.y + wa.w * va3.y;
                sa[2] = wa.x * va0.z + wa.y * va1.z + wa.z * va2.z + wa.w * va3.z;
                sa[3] = wa.x * va0.w + wa.y * va1.w + wa.z * va2.w + wa.w * va3.w;
                sbv[0] = wb.x * vb0.x + wb.y * vb1.x + wb.z * vb2.x + wb.w * vb3.x;
                sbv[1] = wb.x * vb0.y + wb.y * vb1.y + wb.z * vb2.y + wb.w * vb3.y;
                sbv[2] = wb.x * vb0.z + wb.y * vb1.z + wb.z * vb2.z + wb.w * vb3.z;
                sbv[3] = wb.x * vb0.w + wb.y * vb1.w + wb.z * vb2.w + wb.w * vb3.w;
                // swizzled STS.64: quad q = p>>2, q' = q ^ c4
                int q  = p >> 2;
                int qs = q ^ c4;
                float2* Sr = (float2*)(Sbuf + (c4 * 4) * TILE + qs * 4 + half * 2);
#pragma unroll
                for (int u = 0; u < 4; u++)
                    Sr[u * (TILE / 2)] = make_float2(sa[u], sbv[u]);
            }

            MBARRIER_ARRIVE(sb + MB_FULL0 + s * 8);
        }
    } else {
        // ---------------- CONSUMER (4 warps) ----------------
        const int tx = tid & 31;                  // pixel quad (4 pix each)
        const int ty = tid >> 5;                  // o group (16 o each)

        unsigned long long acc[16][2];
#pragma unroll
        for (int oi = 0; oi < 16; oi++) { acc[oi][0] = 0ull; acc[oi][1] = 0ull; }

        for (int k = 0; k < 9; k++) {
            const int s = k & 1;
            const int n = k >> 1;
            MBARRIER_WAIT_PARITY(sb + MB_FULL0 + s * 8, n & 1);

            const float4*     Ws4 = (const float4*)(smc + BUF0 + s * BUFSZ);
            const ulonglong2* Sq  = (const ulonglong2*)(smc + BUF0 + s * BUFSZ + 16384);

#pragma unroll 8
            for (int cc = 0; cc < 64; cc++) {
                int sw = cc >> 2;
                ulonglong2 B = Sq[cc * 32 + (tx ^ sw)];   // 4 pixels, conflict-free
                unsigned long long b0 = B.x, b1 = B.y;
#pragma unroll
                for (int g = 0; g < 4; g++) {
                    float4 av = Ws4[cc * 16 + ty * 4 + g];
                    unsigned long long a0 = pk2(av.x, av.x);
                    unsigned long long a1 = pk2(av.y, av.y);
                    unsigned long long a2 = pk2(av.z, av.z);
                    unsigned long long a3 = pk2(av.w, av.w);
                    fma2(acc[g * 4 + 0][0], a0, b0); fma2(acc[g * 4 + 0][1], a0, b1);
                    fma2(acc[g * 4 + 1][0], a1, b0); fma2(acc[g * 4 + 1][1], a1, b1);
                    fma2(acc[g * 4 + 2][0], a2, b0); fma2(acc[g * 4 + 2][1], a2, b1);
                    fma2(acc[g * 4 + 3][0], a3, b0); fma2(acc[g * 4 + 3][1], a3, b1);
                }
            }

            MBARRIER_ARRIVE(sb + MB_EMPT0 + s * 8);
        }

        // epilogue: 16 o rows x one float4 of pixels
        const int p0 = pbase + tx * 4;
        float* obp = out + (size_t)(b * 64 + ty * 16) * HWp + p0;
#pragma unroll
        for (int oi = 0; oi < 16; oi++) {
            float4 v;
            upk2(acc[oi][0], v.x, v.y);
            upk2(acc[oi][1], v.z, v.w);
            *(float4*)(obp + (size_t)oi * HWp) = v;
        }
    }
}

extern "C" void kernel_launch(void* const* d_in, const int* in_sizes, int n_in,
                              void* d_out, int out_size)
{
    const float* x        = (const float*)d_in[0];
    const float* offset_w = (const float*)d_in[1];
    const float* offset_b = (const float*)d_in[2];
    const float* mask_w   = (const float*)d_in[3];
    const float* mask_b   = (const float*)d_in[4];
    const float* dcn_w    = (const float*)d_in[5];
    float* out = (float*)d_out;

    const int smem1 = 64 * 9 * 28 * 4;      // 64512 B
    cudaFuncSetAttribute(omconv_kernel, cudaFuncAttributeMaxDynamicSharedMemorySize, smem1);
    cudaFuncSetAttribute(dcn_ws_kernel, cudaFuncAttributeMaxDynamicSharedMemorySize, SMEM_WS);

    xpose_kernel<<<dim3(800, 2, 4), dim3(32, 8)>>>(x);
    wpose_kernel<<<144, 256>>>(dcn_w);
    omconv_kernel<<<400, 128, smem1>>>(x, offset_w, offset_b, mask_w, mask_b);
    dcn_ws_kernel<<<800, 256, SMEM_WS>>>(out);
}